// round 11
// baseline (speedup 1.0000x reference)
#include <cuda_runtime.h>
#include <cstdint>

// Problem constants (fixed by the dataset)
#define NMAX 50000
#define FF   4
#define TT   12
#define FT   48   // F*T contiguous floats per node in x layout [N,F,T]
#define CC   32
#define HOR  12
#define CAP  128  // bucket capacity per node (deg ~ Poisson(16); overflow P ~ 1e-60)

typedef unsigned long long u64;

// Scratch (allocation-free: __device__ globals)
__device__ int   g_cnt[NMAX];
__device__ float g_dis[NMAX];
__device__ float g_y[(size_t)NMAX * FT];         // y_i = dis_i * x_i
__device__ __align__(16) int2 g_bucket[(size_t)NMAX * CAP];   // {row, float_bits(w)}
__device__ u64   g_Az2[FF * CC];   // pk2(-L2E*Az, -L2E*Az)
__device__ u64   g_Ah2[FF * CC];   // pk2(-2*L2E*Ah, -2*L2E*Ah)
__device__ u64   g_cz2[CC];
__device__ u64   g_ch2[CC];
__device__ float g_probs[TT];
__device__ int   g_is64;

// Software grid barrier state (persistent kernel)
__device__ unsigned g_bar_arrive = 0;
__device__ volatile unsigned g_bar_gen = 0;

__device__ __forceinline__ void grid_barrier(int nblocks) {
    __syncthreads();
    if (threadIdx.x == 0) {
        __threadfence();
        unsigned gen = g_bar_gen;
        if (atomicAdd(&g_bar_arrive, 1u) == (unsigned)(nblocks - 1)) {
            atomicExch(&g_bar_arrive, 0u);
            __threadfence();
            g_bar_gen = gen + 1;
        } else {
            while (g_bar_gen == gen) { __nanosleep(64); }
            __threadfence();
        }
    }
    __syncthreads();
}

__device__ __forceinline__ int edge_idx(const void* ei, size_t pos, int is64) {
    if (is64) return (int)((const long long*)ei)[pos];
    return ((const int*)ei)[pos];
}

// ---- packed f32x2 helpers (sm_103a) ----
__device__ __forceinline__ u64 pk2(float lo, float hi) {
    u64 r; asm("mov.b64 %0, {%1,%2};" : "=l"(r) : "f"(lo), "f"(hi)); return r;
}
__device__ __forceinline__ void upk2(u64 v, float& lo, float& hi) {
    asm("mov.b64 {%0,%1}, %2;" : "=f"(lo), "=f"(hi) : "l"(v));
}
__device__ __forceinline__ u64 fma2(u64 a, u64 b, u64 c) {
    u64 d; asm("fma.rn.f32x2 %0, %1, %2, %3;" : "=l"(d) : "l"(a), "l"(b), "l"(c)); return d;
}
__device__ __forceinline__ u64 add2(u64 a, u64 b) {
    u64 d; asm("add.rn.f32x2 %0, %1, %2;" : "=l"(d) : "l"(a), "l"(b)); return d;
}
__device__ __forceinline__ u64 mul2(u64 a, u64 b) {
    u64 d; asm("mul.rn.f32x2 %0, %1, %2;" : "=l"(d) : "l"(a), "l"(b)); return d;
}
__device__ __forceinline__ float ex2a(float x) {
    float y; asm("ex2.approx.f32 %0, %1;" : "=f"(y) : "f"(x)); return y;
}
__device__ __forceinline__ float rcpa(float x) {
    float y; asm("rcp.approx.f32 %0, %1;" : "=f"(y) : "f"(x)); return y;
}

// ---------------------------------------------------------------------------
// ONE persistent kernel; phases separated by software grid barriers.
__global__ __launch_bounds__(1024, 1)
void k_mega(const float* __restrict__ x, const void* __restrict__ ei,
            const float* __restrict__ w, const float* __restrict__ att,
            const float* __restrict__ Wz, const float* __restrict__ bz,
            const float* __restrict__ Wlz, const float* __restrict__ blz,
            const float* __restrict__ Wh, const float* __restrict__ bh,
            const float* __restrict__ Wlh, const float* __restrict__ blh,
            const float* __restrict__ Wout, const float* __restrict__ bout,
            float* __restrict__ out, int N, int E, int nblocks)
{
    __shared__ u64   sAz2[FF * CC], sAh2[FF * CC];
    __shared__ u64   scz2[CC], sch2[CC];
    __shared__ float sprobs[TT];
    __shared__ float sWout[CC * HOR], sbout[HOR];
    __shared__ u64   sAfT2[32][24];   // per-warp packed af pairs, [f*6 + tp]
    __shared__ float sH[32][CC];      // per-warp Hacc per channel

    const int tid = threadIdx.x;
    const int bid = blockIdx.x;
    const int gsz = nblocks * 1024;
    const int g   = bid * 1024 + tid;
    const float L2E = 1.4426950408889634f;

    // ---- P0: zero counts; block 0: dtype detect + matrix fusion + softmax
    for (int i = g; i < N; i += gsz) g_cnt[i] = 0;
    if (bid == 0) {
        if (tid < 32) {
            const int* e32 = (const int*)ei;
            int nz = (e32[2 * (2 * tid) + 1] != 0) | (e32[2 * (2 * tid + 1) + 1] != 0);
            unsigned any = __ballot_sync(0xffffffffu, nz);
            if (tid == 0) g_is64 = (any == 0) ? 1 : 0;
        } else if (tid < 160) {
            int t2 = tid - 32;
            int f = t2 >> 5;        // 0..3
            int c = t2 & 31;        // 0..31
            float az = 0.0f, ah = 0.0f;
            #pragma unroll
            for (int k = 0; k < CC; k++) {
                az += Wz[f * CC + k] * Wlz[k * CC + c];
                ah += Wh[f * CC + k] * Wlh[k * CC + c];
            }
            float azs = -L2E * az;
            float ahs = -2.0f * L2E * ah;
            g_Az2[f * CC + c] = pk2(azs, azs);
            g_Ah2[f * CC + c] = pk2(ahs, ahs);
            if (f == 0) {
                float cz = blz[c], ch = blh[c];
                #pragma unroll
                for (int k = 0; k < CC; k++) {
                    cz += bz[k] * Wlz[k * CC + c];
                    ch += bh[k] * Wlh[k * CC + c];
                }
                float czs = -L2E * cz;
                float chs = -2.0f * L2E * ch;
                g_cz2[c] = pk2(czs, czs);
                g_ch2[c] = pk2(chs, chs);
            }
        } else if (tid == 160) {
            float m = att[0];
            for (int t = 1; t < TT; t++) m = fmaxf(m, att[t]);
            float e[TT]; float s = 0.0f;
            for (int t = 0; t < TT; t++) { e[t] = __expf(att[t] - m); s += e[t]; }
            float inv = 1.0f / s;
            for (int t = 0; t < TT; t++) g_probs[t] = e[t] * inv;
        }
    }
    grid_barrier(nblocks);

    const int is64 = g_is64;
    const int lane = tid & 31;
    const int warp0 = g >> 5;
    const int nwarps = gsz >> 5;

    // ---- P1: single-pass bucket fill: {row, w} appended per destination col
    for (int e = g; e < E; e += gsz) {
        int r = edge_idx(ei, (size_t)e, is64);
        int c = edge_idx(ei, (size_t)E + e, is64);
        if ((unsigned)r >= (unsigned)N || (unsigned)c >= (unsigned)N) continue;
        int slot = atomicAdd(&g_cnt[c], 1);
        if (slot < CAP)
            g_bucket[(size_t)c * CAP + slot] = make_int2(r, __float_as_int(w[e]));
    }
    grid_barrier(nblocks);

    // ---- P2: warp-per-node: deg (coalesced + butterfly), dis, y = dis*x
    for (int i = warp0; i < N; i += nwarps) {
        int m = min(g_cnt[i], CAP);
        const int2* b = g_bucket + (size_t)i * CAP;
        float s = 0.0f;
        for (int k = lane; k < m; k += 32) s += __int_as_float(b[k].y);
        s += __shfl_xor_sync(0xffffffffu, s, 1);
        s += __shfl_xor_sync(0xffffffffu, s, 2);
        s += __shfl_xor_sync(0xffffffffu, s, 4);
        s += __shfl_xor_sync(0xffffffffu, s, 8);
        s += __shfl_xor_sync(0xffffffffu, s, 16);
        float dc = rsqrtf(s + 1.0f);
        if (lane == 0) g_dis[i] = dc;
        const float* xi = x + (size_t)i * FT;
        float* yi = g_y + (size_t)i * FT;
        yi[lane] = dc * xi[lane];
        if (lane < 16) yi[lane + 32] = dc * xi[lane + 32];
    }
    grid_barrier(nblocks);

    // ---- P3: gather (packed f32x2 over y) + GRU epilogue, warp per node
    for (int k = tid; k < FF * CC; k += 1024) { sAz2[k] = g_Az2[k]; sAh2[k] = g_Ah2[k]; }
    for (int k = tid; k < CC; k += 1024)      { scz2[k] = g_cz2[k]; sch2[k] = g_ch2[k]; }
    for (int k = tid; k < TT; k += 1024)      sprobs[k] = g_probs[k];
    for (int k = tid; k < CC * HOR; k += 1024) sWout[k] = Wout[k];
    for (int k = tid; k < HOR; k += 1024)      sbout[k] = bout[k];
    __syncthreads();

    const int wid  = tid >> 5;    // warp within block (smem row)
    const int slot = lane >> 2;   // 0..7
    const int p    = lane & 3;    // feature 0..3
    const int c    = lane;        // GRU channel for epilogue

    for (int i = warp0; i < N; i += nwarps) {
        const int2* bkt = g_bucket + (size_t)i * CAP;
        int end = min(g_cnt[i], CAP);

        // packed accumulators: acc2[j] = (xa[2j], xa[2j+1]) for feature p
        u64 acc2[6];
        #pragma unroll
        for (int k = 0; k < 6; k++) acc2[k] = 0ull;

        // paired-edge loop: slot handles edges (2*slot, 2*slot+1), stride 16
        for (int s = slot * 2; s < end; s += 16) {
            int4 bp = *(const int4*)(bkt + s);   // 2 bucket entries, 16B aligned
            {
                float wv = __int_as_float(bp.y);
                u64 w2 = pk2(wv, wv);
                const ulonglong2* yr = (const ulonglong2*)(g_y + (size_t)bp.x * FT + p * 12);
                ulonglong2 q0 = __ldg(yr + 0);
                ulonglong2 q1 = __ldg(yr + 1);
                ulonglong2 q2 = __ldg(yr + 2);
                acc2[0] = fma2(w2, q0.x, acc2[0]);
                acc2[1] = fma2(w2, q0.y, acc2[1]);
                acc2[2] = fma2(w2, q1.x, acc2[2]);
                acc2[3] = fma2(w2, q1.y, acc2[3]);
                acc2[4] = fma2(w2, q2.x, acc2[4]);
                acc2[5] = fma2(w2, q2.y, acc2[5]);
            }
            if (s + 1 < end) {
                float wv = __int_as_float(bp.w);
                u64 w2 = pk2(wv, wv);
                const ulonglong2* yr = (const ulonglong2*)(g_y + (size_t)bp.z * FT + p * 12);
                ulonglong2 q0 = __ldg(yr + 0);
                ulonglong2 q1 = __ldg(yr + 1);
                ulonglong2 q2 = __ldg(yr + 2);
                acc2[0] = fma2(w2, q0.x, acc2[0]);
                acc2[1] = fma2(w2, q0.y, acc2[1]);
                acc2[2] = fma2(w2, q1.x, acc2[2]);
                acc2[3] = fma2(w2, q1.y, acc2[3]);
                acc2[4] = fma2(w2, q2.x, acc2[4]);
                acc2[5] = fma2(w2, q2.y, acc2[5]);
            }
        }

        // reduce over the 8 slots (packed adds)
        #pragma unroll
        for (int k = 0; k < 6; k++) {
            acc2[k] = add2(acc2[k], __shfl_xor_sync(0xffffffffu, acc2[k], 4));
            acc2[k] = add2(acc2[k], __shfl_xor_sync(0xffffffffu, acc2[k], 8));
            acc2[k] = add2(acc2[k], __shfl_xor_sync(0xffffffffu, acc2[k], 16));
        }

        // self + factored dis[col]:  xa = dc * (S + y_i)   [y_i = dc * x_i]
        {
            float dcv = g_dis[i];
            u64 dc2 = pk2(dcv, dcv);
            const ulonglong2* yr = (const ulonglong2*)(g_y + (size_t)i * FT + p * 12);
            ulonglong2 q0 = __ldg(yr + 0);
            ulonglong2 q1 = __ldg(yr + 1);
            ulonglong2 q2 = __ldg(yr + 2);
            acc2[0] = mul2(add2(acc2[0], q0.x), dc2);
            acc2[1] = mul2(add2(acc2[1], q0.y), dc2);
            acc2[2] = mul2(add2(acc2[2], q1.x), dc2);
            acc2[3] = mul2(add2(acc2[3], q1.y), dc2);
            acc2[4] = mul2(add2(acc2[4], q2.x), dc2);
            acc2[5] = mul2(add2(acc2[5], q2.y), dc2);
        }

        // publish packed t-pairs: lane (f = lane&3, tp = lane>>2) for lane<24
        if (lane < 24)
            sAfT2[wid][(lane & 3) * 6 + (lane >> 2)] = acc2[lane >> 2];
        __syncwarp();

        // GRU epilogue: lane owns ONE channel; process t in packed pairs.
        // nz = -L2E*zp, nh = -2*L2E*hp (constants pre-scaled)
        // (1-sigmoid(zp))*tanh(hp) = ez*(1-eh)/((1+ez)(1+eh)), ez=2^nz, eh=2^nh
        float Hacc = 0.0f;
        #pragma unroll
        for (int tp = 0; tp < 6; tp++) {
            u64 a0 = sAfT2[wid][0 * 6 + tp];
            u64 a1 = sAfT2[wid][1 * 6 + tp];
            u64 a2 = sAfT2[wid][2 * 6 + tp];
            u64 a3 = sAfT2[wid][3 * 6 + tp];
            u64 nz2 = scz2[c], nh2 = sch2[c];
            nz2 = fma2(a0, sAz2[0 * CC + c], nz2);
            nz2 = fma2(a1, sAz2[1 * CC + c], nz2);
            nz2 = fma2(a2, sAz2[2 * CC + c], nz2);
            nz2 = fma2(a3, sAz2[3 * CC + c], nz2);
            nh2 = fma2(a0, sAh2[0 * CC + c], nh2);
            nh2 = fma2(a1, sAh2[1 * CC + c], nh2);
            nh2 = fma2(a2, sAh2[2 * CC + c], nh2);
            nh2 = fma2(a3, sAh2[3 * CC + c], nh2);
            float nza, nzb, nha, nhb;
            upk2(nz2, nza, nzb);
            upk2(nh2, nha, nhb);
            float eza = ex2a(nza), eha = ex2a(nha);
            float ezb = ex2a(nzb), ehb = ex2a(nhb);
            float numa = fmaf(eza, -eha, eza);         // ez*(1-eh)
            float numb = fmaf(ezb, -ehb, ezb);
            float dena = (1.0f + eza) * (1.0f + eha);
            float denb = (1.0f + ezb) * (1.0f + ehb);
            float na = sprobs[2 * tp]     * numa;
            float nb = sprobs[2 * tp + 1] * numb;
            float nc = fmaf(na, denb, nb * dena);
            float dc = dena * denb;
            Hacc = fmaf(nc, rcpa(dc), Hacc);           // H0==0 -> Hn=(1-Z)*Ht
        }
        sH[wid][c] = fmaxf(Hacc, 0.0f);
        __syncwarp();

        // projection: lanes 0..11 take channels 0..15, lanes 12..23 take 16..31
        float part = 0.0f;
        int j = (lane < 12) ? lane : lane - 12;
        int k0 = (lane < 12) ? 0 : 16;
        if (lane < 24) {
            #pragma unroll
            for (int k = 0; k < 16; k++)
                part += sH[wid][k0 + k] * sWout[(k0 + k) * HOR + j];
        }
        float other = __shfl_down_sync(0xffffffffu, part, 12);
        if (lane < HOR)
            out[(size_t)i * HOR + lane] = part + other + sbout[lane];
        __syncwarp();
    }
}

// ---------------------------------------------------------------------------
extern "C" void kernel_launch(void* const* d_in, const int* in_sizes, int n_in,
                              void* d_out, int out_size) {
    const float* x    = (const float*)d_in[0];
    const void*  ei   = d_in[1];
    const float* w    = (const float*)d_in[2];
    const float* att  = (const float*)d_in[3];
    const float* Wz   = (const float*)d_in[4];
    const float* bz   = (const float*)d_in[5];
    const float* Wlz  = (const float*)d_in[6];
    const float* blz  = (const float*)d_in[7];
    // d_in[8..11] = Wr, br, Wlr, blr  -- dead (H0 stays zero in the reference)
    const float* Wh   = (const float*)d_in[12];
    const float* bh   = (const float*)d_in[13];
    const float* Wlh  = (const float*)d_in[14];
    const float* blh  = (const float*)d_in[15];
    const float* Wout = (const float*)d_in[16];
    const float* bout = (const float*)d_in[17];
    float*       out  = (float*)d_out;

    int E = in_sizes[2];          // edge_weight element count
    int N = in_sizes[0] / FT;     // x is N*F*T

    int dev = 0, sms = 148;
    cudaGetDevice(&dev);
    cudaDeviceGetAttribute(&sms, cudaDevAttrMultiProcessorCount, dev);

    k_mega<<<sms, 1024>>>(x, ei, w, att, Wz, bz, Wlz, blz,
                          Wh, bh, Wlh, blh, Wout, bout, out, N, E, sms);
}

// round 12
// speedup vs baseline: 1.0285x; 1.0285x over previous
#include <cuda_runtime.h>
#include <cstdint>

// Problem constants (fixed by the dataset)
#define NMAX 50000
#define FF   4
#define TT   12
#define FT   48   // F*T contiguous floats per node in x layout [N,F,T]
#define CC   32
#define HOR  12
#define CAP  128  // bucket capacity per node (deg ~ Poisson(16); overflow P ~ 1e-60)

typedef unsigned long long u64;

// Scratch (allocation-free: __device__ globals)
__device__ int   g_cnt[NMAX];
__device__ float g_dis[NMAX];
__device__ float g_y[(size_t)NMAX * FT];         // y_i = dis_i * x_i
__device__ __align__(16) int2 g_bucket[(size_t)NMAX * CAP];   // {row, float_bits(w)}
__device__ float g_Az[FF * CC];
__device__ float g_Ah[FF * CC];
__device__ float g_cz[CC];
__device__ float g_ch[CC];
__device__ float g_probs[TT];
__device__ int   g_is64;

// Software grid barrier state (persistent kernel)
__device__ unsigned g_bar_arrive = 0;
__device__ volatile unsigned g_bar_gen = 0;

__device__ __forceinline__ void grid_barrier(int nblocks) {
    __syncthreads();
    if (threadIdx.x == 0) {
        __threadfence();
        unsigned gen = g_bar_gen;
        if (atomicAdd(&g_bar_arrive, 1u) == (unsigned)(nblocks - 1)) {
            atomicExch(&g_bar_arrive, 0u);
            __threadfence();
            g_bar_gen = gen + 1;
        } else {
            while (g_bar_gen == gen) { __nanosleep(64); }
            __threadfence();
        }
    }
    __syncthreads();
}

__device__ __forceinline__ int edge_idx(const void* ei, size_t pos, int is64) {
    if (is64) return (int)((const long long*)ei)[pos];
    return ((const int*)ei)[pos];
}

// ---- packed f32x2 helpers (sm_103a) ----
__device__ __forceinline__ u64 pk2(float lo, float hi) {
    u64 r; asm("mov.b64 %0, {%1,%2};" : "=l"(r) : "f"(lo), "f"(hi)); return r;
}
__device__ __forceinline__ void upk2(u64 v, float& lo, float& hi) {
    asm("mov.b64 {%0,%1}, %2;" : "=f"(lo), "=f"(hi) : "l"(v));
}
__device__ __forceinline__ u64 fma2(u64 a, u64 b, u64 c) {
    u64 d; asm("fma.rn.f32x2 %0, %1, %2, %3;" : "=l"(d) : "l"(a), "l"(b), "l"(c)); return d;
}
__device__ __forceinline__ u64 add2(u64 a, u64 b) {
    u64 d; asm("add.rn.f32x2 %0, %1, %2;" : "=l"(d) : "l"(a), "l"(b)); return d;
}
__device__ __forceinline__ u64 mul2(u64 a, u64 b) {
    u64 d; asm("mul.rn.f32x2 %0, %1, %2;" : "=l"(d) : "l"(a), "l"(b)); return d;
}

// ---------------------------------------------------------------------------
// ONE persistent kernel; phases separated by software grid barriers.
__global__ __launch_bounds__(1024, 1)
void k_mega(const float* __restrict__ x, const void* __restrict__ ei,
            const float* __restrict__ w, const float* __restrict__ att,
            const float* __restrict__ Wz, const float* __restrict__ bz,
            const float* __restrict__ Wlz, const float* __restrict__ blz,
            const float* __restrict__ Wh, const float* __restrict__ bh,
            const float* __restrict__ Wlh, const float* __restrict__ blh,
            const float* __restrict__ Wout, const float* __restrict__ bout,
            float* __restrict__ out, int N, int E, int nblocks)
{
    __shared__ float sAz[FF * CC], sAh[FF * CC];
    __shared__ float scz[CC], sch[CC], sprobs[TT];
    __shared__ float sWout[CC * HOR], sbout[HOR];
    __shared__ float sAf[32][FT];    // per-warp af[t*4+f]
    __shared__ float sH[32][CC];     // per-warp Hacc per channel

    const int tid = threadIdx.x;
    const int bid = blockIdx.x;
    const int gsz = nblocks * 1024;
    const int g   = bid * 1024 + tid;

    // ---- P0: zero counts; block 0: dtype detect + matrix fusion + softmax
    for (int i = g; i < N; i += gsz) g_cnt[i] = 0;
    if (bid == 0) {
        if (tid < 32) {
            const int* e32 = (const int*)ei;
            int nz = (e32[2 * (2 * tid) + 1] != 0) | (e32[2 * (2 * tid + 1) + 1] != 0);
            unsigned any = __ballot_sync(0xffffffffu, nz);
            if (tid == 0) g_is64 = (any == 0) ? 1 : 0;
        } else if (tid < 160) {
            int t2 = tid - 32;
            int f = t2 >> 5;        // 0..3
            int c = t2 & 31;        // 0..31
            float az = 0.0f, ah = 0.0f;
            #pragma unroll
            for (int k = 0; k < CC; k++) {
                az += Wz[f * CC + k] * Wlz[k * CC + c];
                ah += Wh[f * CC + k] * Wlh[k * CC + c];
            }
            g_Az[f * CC + c] = az;
            g_Ah[f * CC + c] = ah;
            if (f == 0) {
                float cz = blz[c], ch = blh[c];
                #pragma unroll
                for (int k = 0; k < CC; k++) {
                    cz += bz[k] * Wlz[k * CC + c];
                    ch += bh[k] * Wlh[k * CC + c];
                }
                g_cz[c] = cz;
                g_ch[c] = ch;
            }
        } else if (tid == 160) {
            float m = att[0];
            for (int t = 1; t < TT; t++) m = fmaxf(m, att[t]);
            float e[TT]; float s = 0.0f;
            for (int t = 0; t < TT; t++) { e[t] = __expf(att[t] - m); s += e[t]; }
            float inv = 1.0f / s;
            for (int t = 0; t < TT; t++) g_probs[t] = e[t] * inv;
        }
    }
    grid_barrier(nblocks);

    const int is64 = g_is64;
    const int lane = tid & 31;
    const int warp0 = g >> 5;
    const int nwarps = gsz >> 5;

    // ---- P1: single-pass bucket fill: {row, w} appended per destination col
    for (int e = g; e < E; e += gsz) {
        int r = edge_idx(ei, (size_t)e, is64);
        int c = edge_idx(ei, (size_t)E + e, is64);
        if ((unsigned)r >= (unsigned)N || (unsigned)c >= (unsigned)N) continue;
        int slot = atomicAdd(&g_cnt[c], 1);
        if (slot < CAP)
            g_bucket[(size_t)c * CAP + slot] = make_int2(r, __float_as_int(w[e]));
    }
    grid_barrier(nblocks);

    // ---- P2: warp-per-node: deg (coalesced + butterfly), dis, y = dis*x
    for (int i = warp0; i < N; i += nwarps) {
        int m = min(g_cnt[i], CAP);
        const int2* b = g_bucket + (size_t)i * CAP;
        float s = 0.0f;
        for (int k = lane; k < m; k += 32) s += __int_as_float(b[k].y);
        s += __shfl_xor_sync(0xffffffffu, s, 1);
        s += __shfl_xor_sync(0xffffffffu, s, 2);
        s += __shfl_xor_sync(0xffffffffu, s, 4);
        s += __shfl_xor_sync(0xffffffffu, s, 8);
        s += __shfl_xor_sync(0xffffffffu, s, 16);
        float dc = rsqrtf(s + 1.0f);
        if (lane == 0) g_dis[i] = dc;
        const float* xi = x + (size_t)i * FT;
        float* yi = g_y + (size_t)i * FT;
        yi[lane] = dc * xi[lane];
        if (lane < 16) yi[lane + 32] = dc * xi[lane + 32];
    }
    grid_barrier(nblocks);

    // ---- P3: gather (warp-coalesced rows, packed f32x2) + GRU epilogue
    for (int k = tid; k < FF * CC; k += 1024) { sAz[k] = g_Az[k]; sAh[k] = g_Ah[k]; }
    for (int k = tid; k < CC; k += 1024)      { scz[k] = g_cz[k]; sch[k] = g_ch[k]; }
    for (int k = tid; k < TT; k += 1024)      sprobs[k] = g_probs[k];
    for (int k = tid; k < CC * HOR; k += 1024) sWout[k] = Wout[k];
    for (int k = tid; k < HOR; k += 1024)      sbout[k] = bout[k];
    __syncthreads();

    const int wid = tid >> 5;     // warp within block (smem row)
    const int c   = lane;         // GRU channel for epilogue
    const bool act = (lane < 24); // lanes 0..23 hold the 48-float row as pairs

    for (int i = warp0; i < N; i += nwarps) {
        const int2* bkt = g_bucket + (size_t)i * CAP;
        int end = min(g_cnt[i], CAP);

        // lane l holds y floats [2l, 2l+1] => (f = l/6, t = 2*(l%6), 2*(l%6)+1)
        u64 acca = 0ull, accb = 0ull;

        for (int base = 0; base < end; base += 32) {
            int m = min(32, end - base);
            int2 be = bkt[base + ((lane < m) ? lane : (m - 1))];
            int j = 0;
            for (; j + 2 <= m; j += 2) {
                int   r0 = __shfl_sync(0xffffffffu, be.x, j);
                float w0 = __int_as_float(__shfl_sync(0xffffffffu, be.y, j));
                int   r1 = __shfl_sync(0xffffffffu, be.x, j + 1);
                float w1 = __int_as_float(__shfl_sync(0xffffffffu, be.y, j + 1));
                if (act) {
                    u64 q0 = __ldg((const u64*)(g_y + (size_t)r0 * FT) + lane);
                    u64 q1 = __ldg((const u64*)(g_y + (size_t)r1 * FT) + lane);
                    acca = fma2(pk2(w0, w0), q0, acca);
                    accb = fma2(pk2(w1, w1), q1, accb);
                }
            }
            if (j < m) {
                int   r0 = __shfl_sync(0xffffffffu, be.x, j);
                float w0 = __int_as_float(__shfl_sync(0xffffffffu, be.y, j));
                if (act) {
                    u64 q0 = __ldg((const u64*)(g_y + (size_t)r0 * FT) + lane);
                    acca = fma2(pk2(w0, w0), q0, acca);
                }
            }
        }

        // self + factored dis[col]:  xa = dc * (S + y_i), publish to sAf
        float dcv = g_dis[i];
        if (act) {
            u64 qs = __ldg((const u64*)(g_y + (size_t)i * FT) + lane);
            u64 acc = mul2(add2(add2(acca, accb), qs), pk2(dcv, dcv));
            float alo, ahi;
            upk2(acc, alo, ahi);
            int f  = lane / 6;
            int t0 = 2 * (lane % 6);
            sAf[wid][t0 * 4 + f]       = alo;
            sAf[wid][(t0 + 1) * 4 + f] = ahi;
        }
        __syncwarp();

        // GRU epilogue: each lane owns ONE channel (CC == 32).
        // (1-sigmoid(zp))*tanh(hp) = ez*(1-eh)/((1+ez)*(1+eh)),
        //   ez=e^{-zp}, eh=e^{-2hp}
        float Hacc = 0.0f;
        #pragma unroll
        for (int t = 0; t < TT; t++) {
            float4 af = *(const float4*)&sAf[wid][t * 4];
            float zp = scz[c] + af.x * sAz[0 * CC + c] + af.y * sAz[1 * CC + c]
                              + af.z * sAz[2 * CC + c] + af.w * sAz[3 * CC + c];
            float hp = sch[c] + af.x * sAh[0 * CC + c] + af.y * sAh[1 * CC + c]
                              + af.z * sAh[2 * CC + c] + af.w * sAh[3 * CC + c];
            float ez = __expf(-zp);
            float eh = __expf(-2.0f * hp);
            float num = ez * (1.0f - eh);
            float den = (1.0f + ez) * (1.0f + eh);
            Hacc += sprobs[t] * __fdividef(num, den);   // H0==0 -> Hn=(1-Z)*Ht
        }
        sH[wid][c] = fmaxf(Hacc, 0.0f);
        __syncwarp();

        // projection: lanes 0..11 take channels 0..15, lanes 12..23 take 16..31
        float part = 0.0f;
        int j = (lane < 12) ? lane : lane - 12;
        int k0 = (lane < 12) ? 0 : 16;
        if (lane < 24) {
            #pragma unroll
            for (int k = 0; k < 16; k++)
                part += sH[wid][k0 + k] * sWout[(k0 + k) * HOR + j];
        }
        float other = __shfl_down_sync(0xffffffffu, part, 12);
        if (lane < HOR)
            out[(size_t)i * HOR + lane] = part + other + sbout[lane];
        __syncwarp();
    }
}

// ---------------------------------------------------------------------------
extern "C" void kernel_launch(void* const* d_in, const int* in_sizes, int n_in,
                              void* d_out, int out_size) {
    const float* x    = (const float*)d_in[0];
    const void*  ei   = d_in[1];
    const float* w    = (const float*)d_in[2];
    const float* att  = (const float*)d_in[3];
    const float* Wz   = (const float*)d_in[4];
    const float* bz   = (const float*)d_in[5];
    const float* Wlz  = (const float*)d_in[6];
    const float* blz  = (const float*)d_in[7];
    // d_in[8..11] = Wr, br, Wlr, blr  -- dead (H0 stays zero in the reference)
    const float* Wh   = (const float*)d_in[12];
    const float* bh   = (const float*)d_in[13];
    const float* Wlh  = (const float*)d_in[14];
    const float* blh  = (const float*)d_in[15];
    const float* Wout = (const float*)d_in[16];
    const float* bout = (const float*)d_in[17];
    float*       out  = (float*)d_out;

    int E = in_sizes[2];          // edge_weight element count
    int N = in_sizes[0] / FT;     // x is N*F*T

    int dev = 0, sms = 148;
    cudaGetDevice(&dev);
    cudaDeviceGetAttribute(&sms, cudaDevAttrMultiProcessorCount, dev);

    k_mega<<<sms, 1024>>>(x, ei, w, att, Wz, bz, Wlz, blz,
                          Wh, bh, Wlh, blh, Wout, bout, out, N, E, sms);
}

// round 13
// speedup vs baseline: 1.0490x; 1.0199x over previous
#include <cuda_runtime.h>
#include <cstdint>

// Problem constants (fixed by the dataset)
#define NMAX 50000
#define FF   4
#define TT   12
#define FT   48   // F*T contiguous floats per node in x layout [N,F,T]
#define CC   32
#define HOR  12
#define CAP  128  // bucket capacity per node (deg ~ Poisson(16); overflow P ~ 1e-60)

typedef unsigned long long u64;

// Scratch (allocation-free: __device__ globals)
__device__ int   g_cnt[NMAX];
__device__ float g_dis[NMAX];
__device__ float g_y[(size_t)NMAX * FT];         // y_i = dis_i * x_i
__device__ __align__(16) int2 g_bucket[(size_t)NMAX * CAP];   // {row, float_bits(w)}
__device__ float g_Az[FF * CC];
__device__ float g_Ah[FF * CC];
__device__ float g_cz[CC];
__device__ float g_ch[CC];
__device__ float g_probs[TT];
__device__ int   g_is64;

// Software grid barrier state (persistent kernel)
__device__ unsigned g_bar_arrive = 0;
__device__ volatile unsigned g_bar_gen = 0;

__device__ __forceinline__ void grid_barrier(int nblocks) {
    __syncthreads();
    if (threadIdx.x == 0) {
        __threadfence();
        unsigned gen = g_bar_gen;
        if (atomicAdd(&g_bar_arrive, 1u) == (unsigned)(nblocks - 1)) {
            atomicExch(&g_bar_arrive, 0u);
            __threadfence();
            g_bar_gen = gen + 1;
        } else {
            while (g_bar_gen == gen) { __nanosleep(64); }
            __threadfence();
        }
    }
    __syncthreads();
}

__device__ __forceinline__ int edge_idx(const void* ei, size_t pos, int is64) {
    if (is64) return (int)((const long long*)ei)[pos];
    return ((const int*)ei)[pos];
}

// ---- packed f32x2 helpers (sm_103a) ----
__device__ __forceinline__ u64 pk2(float lo, float hi) {
    u64 r; asm("mov.b64 %0, {%1,%2};" : "=l"(r) : "f"(lo), "f"(hi)); return r;
}
__device__ __forceinline__ void upk2(u64 v, float& lo, float& hi) {
    asm("mov.b64 {%0,%1}, %2;" : "=f"(lo), "=f"(hi) : "l"(v));
}
__device__ __forceinline__ u64 fma2(u64 a, u64 b, u64 c) {
    u64 d; asm("fma.rn.f32x2 %0, %1, %2, %3;" : "=l"(d) : "l"(a), "l"(b), "l"(c)); return d;
}
__device__ __forceinline__ u64 add2(u64 a, u64 b) {
    u64 d; asm("add.rn.f32x2 %0, %1, %2;" : "=l"(d) : "l"(a), "l"(b)); return d;
}
__device__ __forceinline__ u64 mul2(u64 a, u64 b) {
    u64 d; asm("mul.rn.f32x2 %0, %1, %2;" : "=l"(d) : "l"(a), "l"(b)); return d;
}

// ---------------------------------------------------------------------------
// ONE persistent kernel; phases separated by software grid barriers.
__global__ __launch_bounds__(1024, 1)
void k_mega(const float* __restrict__ x, const void* __restrict__ ei,
            const float* __restrict__ w, const float* __restrict__ att,
            const float* __restrict__ Wz, const float* __restrict__ bz,
            const float* __restrict__ Wlz, const float* __restrict__ blz,
            const float* __restrict__ Wh, const float* __restrict__ bh,
            const float* __restrict__ Wlh, const float* __restrict__ blh,
            const float* __restrict__ Wout, const float* __restrict__ bout,
            float* __restrict__ out, int N, int E, int nblocks)
{
    __shared__ float sAz[FF * CC], sAh[FF * CC];
    __shared__ float scz[CC], sch[CC], sprobs[TT];
    __shared__ float sWout[CC * HOR], sbout[HOR];
    __shared__ float sAf[32][FT];    // per-warp af[t*4+f]
    __shared__ float sH[32][CC];     // per-warp Hacc per channel

    const int tid = threadIdx.x;
    const int bid = blockIdx.x;
    const int gsz = nblocks * 1024;
    const int g   = bid * 1024 + tid;

    // ---- P0: zero counts; block 0: dtype detect + matrix fusion + softmax
    for (int i = g; i < N; i += gsz) g_cnt[i] = 0;
    if (bid == 0) {
        if (tid < 32) {
            const int* e32 = (const int*)ei;
            int nz = (e32[2 * (2 * tid) + 1] != 0) | (e32[2 * (2 * tid + 1) + 1] != 0);
            unsigned any = __ballot_sync(0xffffffffu, nz);
            if (tid == 0) g_is64 = (any == 0) ? 1 : 0;
        } else if (tid < 160) {
            int t2 = tid - 32;
            int f = t2 >> 5;        // 0..3
            int c = t2 & 31;        // 0..31
            float az = 0.0f, ah = 0.0f;
            #pragma unroll
            for (int k = 0; k < CC; k++) {
                az += Wz[f * CC + k] * Wlz[k * CC + c];
                ah += Wh[f * CC + k] * Wlh[k * CC + c];
            }
            g_Az[f * CC + c] = az;
            g_Ah[f * CC + c] = ah;
            if (f == 0) {
                float cz = blz[c], ch = blh[c];
                #pragma unroll
                for (int k = 0; k < CC; k++) {
                    cz += bz[k] * Wlz[k * CC + c];
                    ch += bh[k] * Wlh[k * CC + c];
                }
                g_cz[c] = cz;
                g_ch[c] = ch;
            }
        } else if (tid == 160) {
            float m = att[0];
            for (int t = 1; t < TT; t++) m = fmaxf(m, att[t]);
            float e[TT]; float s = 0.0f;
            for (int t = 0; t < TT; t++) { e[t] = __expf(att[t] - m); s += e[t]; }
            float inv = 1.0f / s;
            for (int t = 0; t < TT; t++) g_probs[t] = e[t] * inv;
        }
    }
    grid_barrier(nblocks);

    const int is64 = g_is64;
    const int lane = tid & 31;
    const int warp0 = g >> 5;
    const int nwarps = gsz >> 5;

    // ---- P1: single-pass bucket fill: {row, w} appended per destination col
    for (int e = g; e < E; e += gsz) {
        int r = edge_idx(ei, (size_t)e, is64);
        int c = edge_idx(ei, (size_t)E + e, is64);
        if ((unsigned)r >= (unsigned)N || (unsigned)c >= (unsigned)N) continue;
        int slot = atomicAdd(&g_cnt[c], 1);
        if (slot < CAP)
            g_bucket[(size_t)c * CAP + slot] = make_int2(r, __float_as_int(w[e]));
    }
    grid_barrier(nblocks);

    // ---- P2: warp-per-node: deg (coalesced + butterfly), dis, y = dis*x
    for (int i = warp0; i < N; i += nwarps) {
        int m = min(g_cnt[i], CAP);
        const int2* b = g_bucket + (size_t)i * CAP;
        float s = 0.0f;
        for (int k = lane; k < m; k += 32) s += __int_as_float(b[k].y);
        s += __shfl_xor_sync(0xffffffffu, s, 1);
        s += __shfl_xor_sync(0xffffffffu, s, 2);
        s += __shfl_xor_sync(0xffffffffu, s, 4);
        s += __shfl_xor_sync(0xffffffffu, s, 8);
        s += __shfl_xor_sync(0xffffffffu, s, 16);
        float dc = rsqrtf(s + 1.0f);
        if (lane == 0) g_dis[i] = dc;
        const float* xi = x + (size_t)i * FT;
        float* yi = g_y + (size_t)i * FT;
        yi[lane] = dc * xi[lane];
        if (lane < 16) yi[lane + 32] = dc * xi[lane + 32];
    }
    grid_barrier(nblocks);

    // ---- P3: software-pipelined gather + GRU epilogue, warp per node
    for (int k = tid; k < FF * CC; k += 1024) { sAz[k] = g_Az[k]; sAh[k] = g_Ah[k]; }
    for (int k = tid; k < CC; k += 1024)      { scz[k] = g_cz[k]; sch[k] = g_ch[k]; }
    for (int k = tid; k < TT; k += 1024)      sprobs[k] = g_probs[k];
    for (int k = tid; k < CC * HOR; k += 1024) sWout[k] = Wout[k];
    for (int k = tid; k < HOR; k += 1024)      sbout[k] = bout[k];
    __syncthreads();

    const int wid = tid >> 5;     // warp within block (smem row)
    const int c   = lane;         // GRU channel for epilogue
    const bool act = (lane < 24); // lanes 0..23 hold the 48-float row as pairs

    // ---- prologue prefetch for first node
    int  endP = 0;
    int2 beP  = make_int2(0, 0);
    float disP = 0.0f;
    u64  qsP  = 0ull;
    if (warp0 < N) {
        endP = g_cnt[warp0];
        beP  = __ldg(g_bucket + (size_t)warp0 * CAP + lane);
        disP = g_dis[warp0];
        if (act) qsP = __ldg((const u64*)(g_y + (size_t)warp0 * FT) + lane);
    }

    for (int i = warp0; i < N; i += nwarps) {
        int   end = min(endP, CAP);
        int2  be  = beP;
        float dcv = disP;
        u64   qs  = qsP;

        // lane l holds y floats [2l, 2l+1] => (f = l/6, t = 2*(l%6), 2*(l%6)+1)
        u64 acca = 0ull, accb = 0ull;

        // main: first min(32,end) edges from prefetched be
        int m = min(32, end);
        int j = 0;
        for (; j + 2 <= m; j += 2) {
            int   r0 = __shfl_sync(0xffffffffu, be.x, j);
            float w0 = __int_as_float(__shfl_sync(0xffffffffu, be.y, j));
            int   r1 = __shfl_sync(0xffffffffu, be.x, j + 1);
            float w1 = __int_as_float(__shfl_sync(0xffffffffu, be.y, j + 1));
            if (act) {
                u64 q0 = __ldg((const u64*)(g_y + (size_t)r0 * FT) + lane);
                u64 q1 = __ldg((const u64*)(g_y + (size_t)r1 * FT) + lane);
                acca = fma2(pk2(w0, w0), q0, acca);
                accb = fma2(pk2(w1, w1), q1, accb);
            }
        }
        if (j < m) {
            int   r0 = __shfl_sync(0xffffffffu, be.x, j);
            float w0 = __int_as_float(__shfl_sync(0xffffffffu, be.y, j));
            if (act) {
                u64 q0 = __ldg((const u64*)(g_y + (size_t)r0 * FT) + lane);
                acca = fma2(pk2(w0, w0), q0, acca);
            }
        }
        // rare: deg > 32
        for (int base = 32; base < end; base += 32) {
            int mm = min(32, end - base);
            int2 be2 = __ldg(g_bucket + (size_t)i * CAP + base + lane);
            int jj = 0;
            for (; jj < mm; jj++) {
                int   r0 = __shfl_sync(0xffffffffu, be2.x, jj);
                float w0 = __int_as_float(__shfl_sync(0xffffffffu, be2.y, jj));
                if (act) {
                    u64 q0 = __ldg((const u64*)(g_y + (size_t)r0 * FT) + lane);
                    acca = fma2(pk2(w0, w0), q0, acca);
                }
            }
        }

        // ---- prefetch NEXT node's metadata (latency hides under epilogue)
        int inext = i + nwarps;
        if (inext < N) {
            endP = g_cnt[inext];
            beP  = __ldg(g_bucket + (size_t)inext * CAP + lane);
            disP = g_dis[inext];
            if (act) qsP = __ldg((const u64*)(g_y + (size_t)inext * FT) + lane);
        }

        // self + factored dis[col]:  xa = dc * (S + y_i), publish to sAf
        if (act) {
            u64 acc = mul2(add2(add2(acca, accb), qs), pk2(dcv, dcv));
            float alo, ahi;
            upk2(acc, alo, ahi);
            int f  = lane / 6;
            int t0 = 2 * (lane % 6);
            sAf[wid][t0 * 4 + f]       = alo;
            sAf[wid][(t0 + 1) * 4 + f] = ahi;
        }
        __syncwarp();

        // GRU epilogue: each lane owns ONE channel (CC == 32).
        // (1-sigmoid(zp))*tanh(hp) = ez*(1-eh)/((1+ez)*(1+eh)),
        //   ez=e^{-zp}, eh=e^{-2hp}
        float Hacc = 0.0f;
        #pragma unroll
        for (int t = 0; t < TT; t++) {
            float4 af = *(const float4*)&sAf[wid][t * 4];
            float zp = scz[c] + af.x * sAz[0 * CC + c] + af.y * sAz[1 * CC + c]
                              + af.z * sAz[2 * CC + c] + af.w * sAz[3 * CC + c];
            float hp = sch[c] + af.x * sAh[0 * CC + c] + af.y * sAh[1 * CC + c]
                              + af.z * sAh[2 * CC + c] + af.w * sAh[3 * CC + c];
            float ez = __expf(-zp);
            float eh = __expf(-2.0f * hp);
            float num = ez * (1.0f - eh);
            float den = (1.0f + ez) * (1.0f + eh);
            Hacc += sprobs[t] * __fdividef(num, den);   // H0==0 -> Hn=(1-Z)*Ht
        }
        sH[wid][c] = fmaxf(Hacc, 0.0f);
        __syncwarp();

        // projection: lanes 0..11 take channels 0..15, lanes 12..23 take 16..31
        float part = 0.0f;
        int jj2 = (lane < 12) ? lane : lane - 12;
        int k0 = (lane < 12) ? 0 : 16;
        if (lane < 24) {
            #pragma unroll
            for (int k = 0; k < 16; k++)
                part += sH[wid][k0 + k] * sWout[(k0 + k) * HOR + jj2];
        }
        float other = __shfl_down_sync(0xffffffffu, part, 12);
        if (lane < HOR)
            out[(size_t)i * HOR + lane] = part + other + sbout[lane];
        __syncwarp();
    }
}

// ---------------------------------------------------------------------------
extern "C" void kernel_launch(void* const* d_in, const int* in_sizes, int n_in,
                              void* d_out, int out_size) {
    const float* x    = (const float*)d_in[0];
    const void*  ei   = d_in[1];
    const float* w    = (const float*)d_in[2];
    const float* att  = (const float*)d_in[3];
    const float* Wz   = (const float*)d_in[4];
    const float* bz   = (const float*)d_in[5];
    const float* Wlz  = (const float*)d_in[6];
    const float* blz  = (const float*)d_in[7];
    // d_in[8..11] = Wr, br, Wlr, blr  -- dead (H0 stays zero in the reference)
    const float* Wh   = (const float*)d_in[12];
    const float* bh   = (const float*)d_in[13];
    const float* Wlh  = (const float*)d_in[14];
    const float* blh  = (const float*)d_in[15];
    const float* Wout = (const float*)d_in[16];
    const float* bout = (const float*)d_in[17];
    float*       out  = (float*)d_out;

    int E = in_sizes[2];          // edge_weight element count
    int N = in_sizes[0] / FT;     // x is N*F*T

    int dev = 0, sms = 148;
    cudaGetDevice(&dev);
    cudaDeviceGetAttribute(&sms, cudaDevAttrMultiProcessorCount, dev);

    k_mega<<<sms, 1024>>>(x, ei, w, att, Wz, bz, Wlz, blz,
                          Wh, bh, Wlh, blh, Wout, bout, out, N, E, sms);
}

// round 14
// speedup vs baseline: 1.0768x; 1.0266x over previous
#include <cuda_runtime.h>
#include <cstdint>

// Problem constants (fixed by the dataset)
#define NMAX 50000
#define FF   4
#define TT   12
#define FT   48   // F*T contiguous floats per node in x layout [N,F,T]
#define CC   32
#define HOR  12
#define CAP  128  // bucket capacity per node (deg ~ Poisson(16); overflow P ~ 1e-60)

#define TPB    512              // threads per block
#define BLKSM  3                // co-resident blocks per SM
#define WPB    (TPB / 32)       // warps per block

typedef unsigned long long u64;

// Scratch (allocation-free: __device__ globals)
__device__ int   g_cnt[NMAX];
__device__ float g_dis[NMAX];
__device__ float g_y[(size_t)NMAX * FT];         // y_i = dis_i * x_i
__device__ __align__(16) int2 g_bucket[(size_t)NMAX * CAP];   // {row, float_bits(w)}
__device__ float g_Az[FF * CC];
__device__ float g_Ah[FF * CC];
__device__ float g_cz[CC];
__device__ float g_ch[CC];
__device__ float g_probs[TT];
__device__ int   g_is64;

// Software grid barrier state (persistent kernel)
__device__ unsigned g_bar_arrive = 0;
__device__ volatile unsigned g_bar_gen = 0;

__device__ __forceinline__ void grid_barrier(int nblocks) {
    __syncthreads();
    if (threadIdx.x == 0) {
        __threadfence();
        unsigned gen = g_bar_gen;
        if (atomicAdd(&g_bar_arrive, 1u) == (unsigned)(nblocks - 1)) {
            atomicExch(&g_bar_arrive, 0u);
            __threadfence();
            g_bar_gen = gen + 1;
        } else {
            while (g_bar_gen == gen) { __nanosleep(64); }
            __threadfence();
        }
    }
    __syncthreads();
}

__device__ __forceinline__ int edge_idx(const void* ei, size_t pos, int is64) {
    if (is64) return (int)((const long long*)ei)[pos];
    return ((const int*)ei)[pos];
}

// ---- packed f32x2 helpers (sm_103a) ----
__device__ __forceinline__ u64 pk2(float lo, float hi) {
    u64 r; asm("mov.b64 %0, {%1,%2};" : "=l"(r) : "f"(lo), "f"(hi)); return r;
}
__device__ __forceinline__ void upk2(u64 v, float& lo, float& hi) {
    asm("mov.b64 {%0,%1}, %2;" : "=f"(lo), "=f"(hi) : "l"(v));
}
__device__ __forceinline__ u64 fma2(u64 a, u64 b, u64 c) {
    u64 d; asm("fma.rn.f32x2 %0, %1, %2, %3;" : "=l"(d) : "l"(a), "l"(b), "l"(c)); return d;
}
__device__ __forceinline__ u64 add2(u64 a, u64 b) {
    u64 d; asm("add.rn.f32x2 %0, %1, %2;" : "=l"(d) : "l"(a), "l"(b)); return d;
}
__device__ __forceinline__ u64 mul2(u64 a, u64 b) {
    u64 d; asm("mul.rn.f32x2 %0, %1, %2;" : "=l"(d) : "l"(a), "l"(b)); return d;
}

// ---------------------------------------------------------------------------
// ONE persistent kernel; phases separated by software grid barriers.
// 512 threads x 3 blocks/SM => 48 warps/SM (vs 32 before).
__global__ __launch_bounds__(TPB, BLKSM)
void k_mega(const float* __restrict__ x, const void* __restrict__ ei,
            const float* __restrict__ w, const float* __restrict__ att,
            const float* __restrict__ Wz, const float* __restrict__ bz,
            const float* __restrict__ Wlz, const float* __restrict__ blz,
            const float* __restrict__ Wh, const float* __restrict__ bh,
            const float* __restrict__ Wlh, const float* __restrict__ blh,
            const float* __restrict__ Wout, const float* __restrict__ bout,
            float* __restrict__ out, int N, int E, int nblocks)
{
    __shared__ float sAz[FF * CC], sAh[FF * CC];
    __shared__ float scz[CC], sch[CC], sprobs[TT];
    __shared__ float sWout[CC * HOR], sbout[HOR];
    __shared__ float sAf[WPB][FT];    // per-warp af[t*4+f]
    __shared__ float sH[WPB][CC];     // per-warp Hacc per channel

    const int tid = threadIdx.x;
    const int bid = blockIdx.x;
    const int gsz = nblocks * TPB;
    const int g   = bid * TPB + tid;

    // ---- P0: zero counts; block 0: dtype detect + matrix fusion + softmax
    for (int i = g; i < N; i += gsz) g_cnt[i] = 0;
    if (bid == 0) {
        if (tid < 32) {
            const int* e32 = (const int*)ei;
            int nz = (e32[2 * (2 * tid) + 1] != 0) | (e32[2 * (2 * tid + 1) + 1] != 0);
            unsigned any = __ballot_sync(0xffffffffu, nz);
            if (tid == 0) g_is64 = (any == 0) ? 1 : 0;
        } else if (tid < 160) {
            int t2 = tid - 32;
            int f = t2 >> 5;        // 0..3
            int c = t2 & 31;        // 0..31
            float az = 0.0f, ah = 0.0f;
            #pragma unroll
            for (int k = 0; k < CC; k++) {
                az += Wz[f * CC + k] * Wlz[k * CC + c];
                ah += Wh[f * CC + k] * Wlh[k * CC + c];
            }
            g_Az[f * CC + c] = az;
            g_Ah[f * CC + c] = ah;
            if (f == 0) {
                float cz = blz[c], ch = blh[c];
                #pragma unroll
                for (int k = 0; k < CC; k++) {
                    cz += bz[k] * Wlz[k * CC + c];
                    ch += bh[k] * Wlh[k * CC + c];
                }
                g_cz[c] = cz;
                g_ch[c] = ch;
            }
        } else if (tid == 160) {
            float m = att[0];
            for (int t = 1; t < TT; t++) m = fmaxf(m, att[t]);
            float e[TT]; float s = 0.0f;
            for (int t = 0; t < TT; t++) { e[t] = __expf(att[t] - m); s += e[t]; }
            float inv = 1.0f / s;
            for (int t = 0; t < TT; t++) g_probs[t] = e[t] * inv;
        }
    }
    grid_barrier(nblocks);

    const int is64 = g_is64;
    const int lane = tid & 31;
    const int warp0 = g >> 5;
    const int nwarps = gsz >> 5;

    // ---- P1: single-pass bucket fill: {row, w} appended per destination col
    for (int e = g; e < E; e += gsz) {
        int r = edge_idx(ei, (size_t)e, is64);
        int c = edge_idx(ei, (size_t)E + e, is64);
        if ((unsigned)r >= (unsigned)N || (unsigned)c >= (unsigned)N) continue;
        int slot = atomicAdd(&g_cnt[c], 1);
        if (slot < CAP)
            g_bucket[(size_t)c * CAP + slot] = make_int2(r, __float_as_int(w[e]));
    }
    grid_barrier(nblocks);

    // ---- P2: warp-per-node: deg (coalesced + butterfly), dis, y = dis*x
    for (int i = warp0; i < N; i += nwarps) {
        int m = min(g_cnt[i], CAP);
        const int2* b = g_bucket + (size_t)i * CAP;
        float s = 0.0f;
        for (int k = lane; k < m; k += 32) s += __int_as_float(b[k].y);
        s += __shfl_xor_sync(0xffffffffu, s, 1);
        s += __shfl_xor_sync(0xffffffffu, s, 2);
        s += __shfl_xor_sync(0xffffffffu, s, 4);
        s += __shfl_xor_sync(0xffffffffu, s, 8);
        s += __shfl_xor_sync(0xffffffffu, s, 16);
        float dc = rsqrtf(s + 1.0f);
        if (lane == 0) g_dis[i] = dc;
        const float* xi = x + (size_t)i * FT;
        float* yi = g_y + (size_t)i * FT;
        yi[lane] = dc * xi[lane];
        if (lane < 16) yi[lane + 32] = dc * xi[lane + 32];
    }
    grid_barrier(nblocks);

    // ---- P3: software-pipelined gather + GRU epilogue, warp per node
    for (int k = tid; k < FF * CC; k += TPB) { sAz[k] = g_Az[k]; sAh[k] = g_Ah[k]; }
    for (int k = tid; k < CC; k += TPB)      { scz[k] = g_cz[k]; sch[k] = g_ch[k]; }
    for (int k = tid; k < TT; k += TPB)      sprobs[k] = g_probs[k];
    for (int k = tid; k < CC * HOR; k += TPB) sWout[k] = Wout[k];
    for (int k = tid; k < HOR; k += TPB)      sbout[k] = bout[k];
    __syncthreads();

    const int wid = tid >> 5;     // warp within block (smem row)
    const int c   = lane;         // GRU channel for epilogue
    const bool act = (lane < 24); // lanes 0..23 hold the 48-float row as pairs

    // ---- prologue prefetch for first node
    int  endP = 0;
    int2 beP  = make_int2(0, 0);
    float disP = 0.0f;
    u64  qsP  = 0ull;
    if (warp0 < N) {
        endP = g_cnt[warp0];
        beP  = __ldg(g_bucket + (size_t)warp0 * CAP + lane);
        disP = g_dis[warp0];
        if (act) qsP = __ldg((const u64*)(g_y + (size_t)warp0 * FT) + lane);
    }

    for (int i = warp0; i < N; i += nwarps) {
        int   end = min(endP, CAP);
        int2  be  = beP;
        float dcv = disP;
        u64   qs  = qsP;

        // lane l holds y floats [2l, 2l+1] => (f = l/6, t = 2*(l%6), 2*(l%6)+1)
        u64 acca = 0ull, accb = 0ull;

        // main: first min(32,end) edges from prefetched be
        int m = min(32, end);
        int j = 0;
        for (; j + 2 <= m; j += 2) {
            int   r0 = __shfl_sync(0xffffffffu, be.x, j);
            float w0 = __int_as_float(__shfl_sync(0xffffffffu, be.y, j));
            int   r1 = __shfl_sync(0xffffffffu, be.x, j + 1);
            float w1 = __int_as_float(__shfl_sync(0xffffffffu, be.y, j + 1));
            if (act) {
                u64 q0 = __ldg((const u64*)(g_y + (size_t)r0 * FT) + lane);
                u64 q1 = __ldg((const u64*)(g_y + (size_t)r1 * FT) + lane);
                acca = fma2(pk2(w0, w0), q0, acca);
                accb = fma2(pk2(w1, w1), q1, accb);
            }
        }
        if (j < m) {
            int   r0 = __shfl_sync(0xffffffffu, be.x, j);
            float w0 = __int_as_float(__shfl_sync(0xffffffffu, be.y, j));
            if (act) {
                u64 q0 = __ldg((const u64*)(g_y + (size_t)r0 * FT) + lane);
                acca = fma2(pk2(w0, w0), q0, acca);
            }
        }
        // rare: deg > 32
        for (int base = 32; base < end; base += 32) {
            int mm = min(32, end - base);
            int2 be2 = __ldg(g_bucket + (size_t)i * CAP + base + lane);
            int jj = 0;
            for (; jj < mm; jj++) {
                int   r0 = __shfl_sync(0xffffffffu, be2.x, jj);
                float w0 = __int_as_float(__shfl_sync(0xffffffffu, be2.y, jj));
                if (act) {
                    u64 q0 = __ldg((const u64*)(g_y + (size_t)r0 * FT) + lane);
                    acca = fma2(pk2(w0, w0), q0, acca);
                }
            }
        }

        // ---- prefetch NEXT node's metadata (latency hides under epilogue)
        int inext = i + nwarps;
        if (inext < N) {
            endP = g_cnt[inext];
            beP  = __ldg(g_bucket + (size_t)inext * CAP + lane);
            disP = g_dis[inext];
            if (act) qsP = __ldg((const u64*)(g_y + (size_t)inext * FT) + lane);
        }

        // self + factored dis[col]:  xa = dc * (S + y_i), publish to sAf
        if (act) {
            u64 acc = mul2(add2(add2(acca, accb), qs), pk2(dcv, dcv));
            float alo, ahi;
            upk2(acc, alo, ahi);
            int f  = lane / 6;
            int t0 = 2 * (lane % 6);
            sAf[wid][t0 * 4 + f]       = alo;
            sAf[wid][(t0 + 1) * 4 + f] = ahi;
        }
        __syncwarp();

        // GRU epilogue: each lane owns ONE channel (CC == 32).
        // (1-sigmoid(zp))*tanh(hp) = ez*(1-eh)/((1+ez)*(1+eh)),
        //   ez=e^{-zp}, eh=e^{-2hp}
        float Hacc = 0.0f;
        #pragma unroll
        for (int t = 0; t < TT; t++) {
            float4 af = *(const float4*)&sAf[wid][t * 4];
            float zp = scz[c] + af.x * sAz[0 * CC + c] + af.y * sAz[1 * CC + c]
                              + af.z * sAz[2 * CC + c] + af.w * sAz[3 * CC + c];
            float hp = sch[c] + af.x * sAh[0 * CC + c] + af.y * sAh[1 * CC + c]
                              + af.z * sAh[2 * CC + c] + af.w * sAh[3 * CC + c];
            float ez = __expf(-zp);
            float eh = __expf(-2.0f * hp);
            float num = ez * (1.0f - eh);
            float den = (1.0f + ez) * (1.0f + eh);
            Hacc += sprobs[t] * __fdividef(num, den);   // H0==0 -> Hn=(1-Z)*Ht
        }
        sH[wid][c] = fmaxf(Hacc, 0.0f);
        __syncwarp();

        // projection: lanes 0..11 take channels 0..15, lanes 12..23 take 16..31
        float part = 0.0f;
        int jj2 = (lane < 12) ? lane : lane - 12;
        int k0 = (lane < 12) ? 0 : 16;
        if (lane < 24) {
            #pragma unroll
            for (int k = 0; k < 16; k++)
                part += sH[wid][k0 + k] * sWout[(k0 + k) * HOR + jj2];
        }
        float other = __shfl_down_sync(0xffffffffu, part, 12);
        if (lane < HOR)
            out[(size_t)i * HOR + lane] = part + other + sbout[lane];
        __syncwarp();
    }
}

// ---------------------------------------------------------------------------
extern "C" void kernel_launch(void* const* d_in, const int* in_sizes, int n_in,
                              void* d_out, int out_size) {
    const float* x    = (const float*)d_in[0];
    const void*  ei   = d_in[1];
    const float* w    = (const float*)d_in[2];
    const float* att  = (const float*)d_in[3];
    const float* Wz   = (const float*)d_in[4];
    const float* bz   = (const float*)d_in[5];
    const float* Wlz  = (const float*)d_in[6];
    const float* blz  = (const float*)d_in[7];
    // d_in[8..11] = Wr, br, Wlr, blr  -- dead (H0 stays zero in the reference)
    const float* Wh   = (const float*)d_in[12];
    const float* bh   = (const float*)d_in[13];
    const float* Wlh  = (const float*)d_in[14];
    const float* blh  = (const float*)d_in[15];
    const float* Wout = (const float*)d_in[16];
    const float* bout = (const float*)d_in[17];
    float*       out  = (float*)d_out;

    int E = in_sizes[2];          // edge_weight element count
    int N = in_sizes[0] / FT;     // x is N*F*T

    int dev = 0, sms = 148;
    cudaGetDevice(&dev);
    cudaDeviceGetAttribute(&sms, cudaDevAttrMultiProcessorCount, dev);

    int nblocks = sms * BLKSM;
    k_mega<<<nblocks, TPB>>>(x, ei, w, att, Wz, bz, Wlz, blz,
                             Wh, bh, Wlh, blh, Wout, bout, out, N, E, nblocks);
}

// round 15
// speedup vs baseline: 1.1011x; 1.0226x over previous
#include <cuda_runtime.h>
#include <cstdint>

// Problem constants (fixed by the dataset)
#define NMAX 50000
#define FF   4
#define TT   12
#define FT   48   // F*T contiguous floats per node in x layout [N,F,T]
#define CC   32
#define HOR  12
#define CAP  128  // bucket capacity per node (deg ~ Poisson(16); overflow P ~ 1e-60)

#define TPB    512              // threads per block
#define BLKSM  3                // co-resident blocks per SM
#define WPB    (TPB / 32)       // warps per block

typedef unsigned long long u64;

// Scratch (allocation-free: __device__ globals)
__device__ int   g_cnt[NMAX];
__device__ float g_dis[NMAX];
__device__ float g_y[(size_t)NMAX * FT];         // y_i = dis_i * x_i
__device__ __align__(16) int2 g_bucket[(size_t)NMAX * CAP];   // {row, float_bits(w)}
__device__ float g_Az[FF * CC];   // scaled by -log2(e)
__device__ float g_Ah[FF * CC];   // scaled by -2*log2(e)
__device__ float g_cz[CC];        // scaled by -log2(e)
__device__ float g_ch[CC];        // scaled by -2*log2(e)
__device__ float g_probs[TT];
__device__ int   g_is64;

// Software grid barrier state (persistent kernel)
__device__ unsigned g_bar_arrive = 0;
__device__ volatile unsigned g_bar_gen = 0;

__device__ __forceinline__ void grid_barrier(int nblocks) {
    __syncthreads();
    if (threadIdx.x == 0) {
        __threadfence();
        unsigned gen = g_bar_gen;
        if (atomicAdd(&g_bar_arrive, 1u) == (unsigned)(nblocks - 1)) {
            atomicExch(&g_bar_arrive, 0u);
            __threadfence();
            g_bar_gen = gen + 1;
        } else {
            while (g_bar_gen == gen) { __nanosleep(64); }
            __threadfence();
        }
    }
    __syncthreads();
}

__device__ __forceinline__ int edge_idx(const void* ei, size_t pos, int is64) {
    if (is64) return (int)((const long long*)ei)[pos];
    return ((const int*)ei)[pos];
}

// ---- packed f32x2 helpers (sm_103a) ----
__device__ __forceinline__ u64 pk2(float lo, float hi) {
    u64 r; asm("mov.b64 %0, {%1,%2};" : "=l"(r) : "f"(lo), "f"(hi)); return r;
}
__device__ __forceinline__ void upk2(u64 v, float& lo, float& hi) {
    asm("mov.b64 {%0,%1}, %2;" : "=f"(lo), "=f"(hi) : "l"(v));
}
__device__ __forceinline__ u64 fma2(u64 a, u64 b, u64 c) {
    u64 d; asm("fma.rn.f32x2 %0, %1, %2, %3;" : "=l"(d) : "l"(a), "l"(b), "l"(c)); return d;
}
__device__ __forceinline__ u64 add2(u64 a, u64 b) {
    u64 d; asm("add.rn.f32x2 %0, %1, %2;" : "=l"(d) : "l"(a), "l"(b)); return d;
}
__device__ __forceinline__ u64 mul2(u64 a, u64 b) {
    u64 d; asm("mul.rn.f32x2 %0, %1, %2;" : "=l"(d) : "l"(a), "l"(b)); return d;
}
__device__ __forceinline__ float ex2a(float x) {
    float y; asm("ex2.approx.f32 %0, %1;" : "=f"(y) : "f"(x)); return y;
}
__device__ __forceinline__ float rcpa(float x) {
    float y; asm("rcp.approx.f32 %0, %1;" : "=f"(y) : "f"(x)); return y;
}

// ---------------------------------------------------------------------------
// ONE persistent kernel; phases separated by software grid barriers.
__global__ __launch_bounds__(TPB, BLKSM)
void k_mega(const float* __restrict__ x, const void* __restrict__ ei,
            const float* __restrict__ w, const float* __restrict__ att,
            const float* __restrict__ Wz, const float* __restrict__ bz,
            const float* __restrict__ Wlz, const float* __restrict__ blz,
            const float* __restrict__ Wh, const float* __restrict__ bh,
            const float* __restrict__ Wlh, const float* __restrict__ blh,
            const float* __restrict__ Wout, const float* __restrict__ bout,
            float* __restrict__ out, int N, int E, int nblocks)
{
    __shared__ float sAz[FF * CC], sAh[FF * CC];
    __shared__ float scz[CC], sch[CC], sprobs[TT];
    __shared__ float sWout[CC * HOR], sbout[HOR];
    __shared__ float sAf[WPB][FT];    // per-warp af[t*4+f]
    __shared__ float sH[WPB][CC];     // per-warp Hacc per channel

    const int tid = threadIdx.x;
    const int bid = blockIdx.x;
    const int gsz = nblocks * TPB;
    const int g   = bid * TPB + tid;
    const float L2E = 1.4426950408889634f;

    // ---- P0: zero counts; block 0: dtype detect + matrix fusion + softmax
    for (int i = g; i < N; i += gsz) g_cnt[i] = 0;
    if (bid == 0) {
        if (tid < 32) {
            const int* e32 = (const int*)ei;
            int nz = (e32[2 * (2 * tid) + 1] != 0) | (e32[2 * (2 * tid + 1) + 1] != 0);
            unsigned any = __ballot_sync(0xffffffffu, nz);
            if (tid == 0) g_is64 = (any == 0) ? 1 : 0;
        } else if (tid < 160) {
            int t2 = tid - 32;
            int f = t2 >> 5;        // 0..3
            int c = t2 & 31;        // 0..31
            float az = 0.0f, ah = 0.0f;
            #pragma unroll
            for (int k = 0; k < CC; k++) {
                az += Wz[f * CC + k] * Wlz[k * CC + c];
                ah += Wh[f * CC + k] * Wlh[k * CC + c];
            }
            g_Az[f * CC + c] = -L2E * az;          // prescaled: nz = log2(e^{-zp})
            g_Ah[f * CC + c] = -2.0f * L2E * ah;   // prescaled: nh = log2(e^{-2hp})
            if (f == 0) {
                float cz = blz[c], ch = blh[c];
                #pragma unroll
                for (int k = 0; k < CC; k++) {
                    cz += bz[k] * Wlz[k * CC + c];
                    ch += bh[k] * Wlh[k * CC + c];
                }
                g_cz[c] = -L2E * cz;
                g_ch[c] = -2.0f * L2E * ch;
            }
        } else if (tid == 160) {
            float m = att[0];
            for (int t = 1; t < TT; t++) m = fmaxf(m, att[t]);
            float e[TT]; float s = 0.0f;
            for (int t = 0; t < TT; t++) { e[t] = __expf(att[t] - m); s += e[t]; }
            float inv = 1.0f / s;
            for (int t = 0; t < TT; t++) g_probs[t] = e[t] * inv;
        }
    }
    grid_barrier(nblocks);

    const int is64 = g_is64;
    const int lane = tid & 31;
    const int warp0 = g >> 5;
    const int nwarps = gsz >> 5;

    // ---- P1: single-pass bucket fill: {row, w} appended per destination col
    if (!is64) {
        // int32 fast path: 2 edges per thread, vector loads
        const int* e32 = (const int*)ei;
        int Ep = E & ~1;
        for (int e = g * 2; e < Ep; e += gsz * 2) {
            int2   rr = *(const int2*)(e32 + e);
            int2   cc = *(const int2*)(e32 + E + e);
            float2 ww = *(const float2*)(w + e);
            if ((unsigned)rr.x < (unsigned)N && (unsigned)cc.x < (unsigned)N) {
                int slot = atomicAdd(&g_cnt[cc.x], 1);
                if (slot < CAP)
                    g_bucket[(size_t)cc.x * CAP + slot] = make_int2(rr.x, __float_as_int(ww.x));
            }
            if ((unsigned)rr.y < (unsigned)N && (unsigned)cc.y < (unsigned)N) {
                int slot = atomicAdd(&g_cnt[cc.y], 1);
                if (slot < CAP)
                    g_bucket[(size_t)cc.y * CAP + slot] = make_int2(rr.y, __float_as_int(ww.y));
            }
        }
        if ((E & 1) && g == 0) {
            int e = E - 1;
            int r = e32[e], c = e32[E + e];
            if ((unsigned)r < (unsigned)N && (unsigned)c < (unsigned)N) {
                int slot = atomicAdd(&g_cnt[c], 1);
                if (slot < CAP)
                    g_bucket[(size_t)c * CAP + slot] = make_int2(r, __float_as_int(w[e]));
            }
        }
    } else {
        for (int e = g; e < E; e += gsz) {
            int r = edge_idx(ei, (size_t)e, is64);
            int c = edge_idx(ei, (size_t)E + e, is64);
            if ((unsigned)r >= (unsigned)N || (unsigned)c >= (unsigned)N) continue;
            int slot = atomicAdd(&g_cnt[c], 1);
            if (slot < CAP)
                g_bucket[(size_t)c * CAP + slot] = make_int2(r, __float_as_int(w[e]));
        }
    }
    grid_barrier(nblocks);

    // ---- P2: warp-per-node: deg (coalesced + butterfly), dis, y = dis*x
    for (int i = warp0; i < N; i += nwarps) {
        int m = min(g_cnt[i], CAP);
        const int2* b = g_bucket + (size_t)i * CAP;
        float s = 0.0f;
        for (int k = lane; k < m; k += 32) s += __int_as_float(b[k].y);
        s += __shfl_xor_sync(0xffffffffu, s, 1);
        s += __shfl_xor_sync(0xffffffffu, s, 2);
        s += __shfl_xor_sync(0xffffffffu, s, 4);
        s += __shfl_xor_sync(0xffffffffu, s, 8);
        s += __shfl_xor_sync(0xffffffffu, s, 16);
        float dc = rsqrtf(s + 1.0f);
        if (lane == 0) g_dis[i] = dc;
        const float* xi = x + (size_t)i * FT;
        float* yi = g_y + (size_t)i * FT;
        yi[lane] = dc * xi[lane];
        if (lane < 16) yi[lane + 32] = dc * xi[lane + 32];
    }
    grid_barrier(nblocks);

    // ---- P3: software-pipelined gather + GRU epilogue, warp per node
    for (int k = tid; k < FF * CC; k += TPB) { sAz[k] = g_Az[k]; sAh[k] = g_Ah[k]; }
    for (int k = tid; k < CC; k += TPB)      { scz[k] = g_cz[k]; sch[k] = g_ch[k]; }
    for (int k = tid; k < TT; k += TPB)      sprobs[k] = g_probs[k];
    for (int k = tid; k < CC * HOR; k += TPB) sWout[k] = Wout[k];
    for (int k = tid; k < HOR; k += TPB)      sbout[k] = bout[k];
    __syncthreads();

    const int wid = tid >> 5;     // warp within block (smem row)
    const int c   = lane;         // GRU channel for epilogue
    const bool act = (lane < 24); // lanes 0..23 hold the 48-float row as pairs

    // ---- prologue prefetch for first node
    int  endP = 0;
    int2 beP  = make_int2(0, 0);
    float disP = 0.0f;
    u64  qsP  = 0ull;
    if (warp0 < N) {
        endP = g_cnt[warp0];
        beP  = __ldg(g_bucket + (size_t)warp0 * CAP + lane);
        disP = g_dis[warp0];
        if (act) qsP = __ldg((const u64*)(g_y + (size_t)warp0 * FT) + lane);
    }

    for (int i = warp0; i < N; i += nwarps) {
        int   end = min(endP, CAP);
        int2  be  = beP;
        float dcv = disP;
        u64   qs  = qsP;

        // lane l holds y floats [2l, 2l+1] => (f = l/6, t = 2*(l%6), 2*(l%6)+1)
        u64 acca = 0ull, accb = 0ull;

        // main: first min(32,end) edges from prefetched be
        int m = min(32, end);
        int j = 0;
        for (; j + 2 <= m; j += 2) {
            int   r0 = __shfl_sync(0xffffffffu, be.x, j);
            float w0 = __int_as_float(__shfl_sync(0xffffffffu, be.y, j));
            int   r1 = __shfl_sync(0xffffffffu, be.x, j + 1);
            float w1 = __int_as_float(__shfl_sync(0xffffffffu, be.y, j + 1));
            if (act) {
                u64 q0 = __ldg((const u64*)(g_y + (size_t)r0 * FT) + lane);
                u64 q1 = __ldg((const u64*)(g_y + (size_t)r1 * FT) + lane);
                acca = fma2(pk2(w0, w0), q0, acca);
                accb = fma2(pk2(w1, w1), q1, accb);
            }
        }
        if (j < m) {
            int   r0 = __shfl_sync(0xffffffffu, be.x, j);
            float w0 = __int_as_float(__shfl_sync(0xffffffffu, be.y, j));
            if (act) {
                u64 q0 = __ldg((const u64*)(g_y + (size_t)r0 * FT) + lane);
                acca = fma2(pk2(w0, w0), q0, acca);
            }
        }
        // rare: deg > 32
        for (int base = 32; base < end; base += 32) {
            int mm = min(32, end - base);
            int2 be2 = __ldg(g_bucket + (size_t)i * CAP + base + lane);
            for (int jj = 0; jj < mm; jj++) {
                int   r0 = __shfl_sync(0xffffffffu, be2.x, jj);
                float w0 = __int_as_float(__shfl_sync(0xffffffffu, be2.y, jj));
                if (act) {
                    u64 q0 = __ldg((const u64*)(g_y + (size_t)r0 * FT) + lane);
                    acca = fma2(pk2(w0, w0), q0, acca);
                }
            }
        }

        // ---- prefetch NEXT node's metadata (latency hides under epilogue)
        int inext = i + nwarps;
        if (inext < N) {
            endP = g_cnt[inext];
            beP  = __ldg(g_bucket + (size_t)inext * CAP + lane);
            disP = g_dis[inext];
            if (act) qsP = __ldg((const u64*)(g_y + (size_t)inext * FT) + lane);
        }

        // self + factored dis[col]:  xa = dc * (S + y_i), publish to sAf
        if (act) {
            u64 acc = mul2(add2(add2(acca, accb), qs), pk2(dcv, dcv));
            float alo, ahi;
            upk2(acc, alo, ahi);
            int f  = lane / 6;
            int t0 = 2 * (lane % 6);
            sAf[wid][t0 * 4 + f]       = alo;
            sAf[wid][(t0 + 1) * 4 + f] = ahi;
        }
        __syncwarp();

        // GRU epilogue: lane owns ONE channel; t processed in pairs.
        // nz = log2(e^{-zp}) via prescaled constants; ez = 2^nz, eh = 2^nh
        // (1-sigmoid(zp))*tanh(hp) = ez*(1-eh)/((1+ez)(1+eh))
        // pair-combined: p0*n0/d0 + p1*n1/d1 = (p0n0d1 + p1n1d0)*rcp(d0*d1)
        float Hacc = 0.0f;
        #pragma unroll
        for (int tp = 0; tp < 6; tp++) {
            float4 af0 = *(const float4*)&sAf[wid][(2 * tp) * 4];
            float4 af1 = *(const float4*)&sAf[wid][(2 * tp + 1) * 4];
            float nz0 = scz[c] + af0.x * sAz[0 * CC + c] + af0.y * sAz[1 * CC + c]
                               + af0.z * sAz[2 * CC + c] + af0.w * sAz[3 * CC + c];
            float nh0 = sch[c] + af0.x * sAh[0 * CC + c] + af0.y * sAh[1 * CC + c]
                               + af0.z * sAh[2 * CC + c] + af0.w * sAh[3 * CC + c];
            float nz1 = scz[c] + af1.x * sAz[0 * CC + c] + af1.y * sAz[1 * CC + c]
                               + af1.z * sAz[2 * CC + c] + af1.w * sAz[3 * CC + c];
            float nh1 = sch[c] + af1.x * sAh[0 * CC + c] + af1.y * sAh[1 * CC + c]
                               + af1.z * sAh[2 * CC + c] + af1.w * sAh[3 * CC + c];
            float ez0 = ex2a(nz0), eh0 = ex2a(nh0);
            float ez1 = ex2a(nz1), eh1 = ex2a(nh1);
            float num0 = fmaf(ez0, -eh0, ez0);       // ez*(1-eh)
            float num1 = fmaf(ez1, -eh1, ez1);
            float den0 = (1.0f + ez0) * (1.0f + eh0);
            float den1 = (1.0f + ez1) * (1.0f + eh1);
            float nsum = fmaf(sprobs[2 * tp] * num0, den1,
                              sprobs[2 * tp + 1] * num1 * den0);
            Hacc = fmaf(nsum, rcpa(den0 * den1), Hacc);   // H0==0 -> Hn=(1-Z)*Ht
        }
        sH[wid][c] = fmaxf(Hacc, 0.0f);
        __syncwarp();

        // projection: lanes 0..11 take channels 0..15, lanes 12..23 take 16..31
        float part = 0.0f;
        int jj2 = (lane < 12) ? lane : lane - 12;
        int k0 = (lane < 12) ? 0 : 16;
        if (lane < 24) {
            #pragma unroll
            for (int k = 0; k < 16; k++)
                part += sH[wid][k0 + k] * sWout[(k0 + k) * HOR + jj2];
        }
        float other = __shfl_down_sync(0xffffffffu, part, 12);
        if (lane < HOR)
            out[(size_t)i * HOR + lane] = part + other + sbout[lane];
        __syncwarp();
    }
}

// ---------------------------------------------------------------------------
extern "C" void kernel_launch(void* const* d_in, const int* in_sizes, int n_in,
                              void* d_out, int out_size) {
    const float* x    = (const float*)d_in[0];
    const void*  ei   = d_in[1];
    const float* w    = (const float*)d_in[2];
    const float* att  = (const float*)d_in[3];
    const float* Wz   = (const float*)d_in[4];
    const float* bz   = (const float*)d_in[5];
    const float* Wlz  = (const float*)d_in[6];
    const float* blz  = (const float*)d_in[7];
    // d_in[8..11] = Wr, br, Wlr, blr  -- dead (H0 stays zero in the reference)
    const float* Wh   = (const float*)d_in[12];
    const float* bh   = (const float*)d_in[13];
    const float* Wlh  = (const float*)d_in[14];
    const float* blh  = (const float*)d_in[15];
    const float* Wout = (const float*)d_in[16];
    const float* bout = (const float*)d_in[17];
    float*       out  = (float*)d_out;

    int E = in_sizes[2];          // edge_weight element count
    int N = in_sizes[0] / FT;     // x is N*F*T

    int dev = 0, sms = 148;
    cudaGetDevice(&dev);
    cudaDeviceGetAttribute(&sms, cudaDevAttrMultiProcessorCount, dev);

    int nblocks = sms * BLKSM;
    k_mega<<<nblocks, TPB>>>(x, ei, w, att, Wz, bz, Wlz, blz,
                             Wh, bh, Wlh, blh, Wout, bout, out, N, E, nblocks);
}